// round 13
// baseline (speedup 1.0000x reference)
#include <cuda_runtime.h>
#include <cstdint>

#define VOCAB  50000
#define EMBED  256
#define MAXLEN 512
#define UNITS  32
#define F1     16
#define BATCH  512
#define PHASE  256     // steps staged per SMEM refill

// Scratch: projected embedding table P[v][u] = sum_e emb[v][e]*Wx[e][u], prescaled
// by 2*log2(e) so the recurrence can feed ex2 directly.
__device__ float g_P[VOCAB * UNITS];

#define TANH_SCALE 2.8853900817779268f   // 2*log2(e)

// Dynamic SMEM layout (per block of 4 warps):
//   [0, 131072)        sXW : 4 warps x (PHASE/4) groups x 32 lanes x 4 floats
//   [131072, 139264)   sTok: 4 x MAXLEN ints
//   [139264, 139776)   sR  : 4 x 32 floats (broadcast rows, 128B each)
#define SMEM_XW   0
#define SMEM_TOK  131072
#define SMEM_R    139264
#define SMEM_TOTAL 139776

// ---------------------------------------------------------------------------
// Kernel A: P = (emb_table @ Wx) * TANH_SCALE  (scalar; measured at the fp32
// FMA-issue floor ~12-13us for 0.41G MACs; not the bottleneck)
// ---------------------------------------------------------------------------
__global__ void __launch_bounds__(128) proj_kernel(
    const float* __restrict__ emb, const float* __restrict__ Wx)
{
    __shared__ float sW[EMBED * UNITS];
    const int t = threadIdx.x;
    for (int i = t; i < EMBED * UNITS / 4; i += 128)
        ((float4*)sW)[i] = ((const float4*)Wx)[i];
    __syncthreads();

    const int ug    = t & 3;
    const int s     = t >> 2;
    const int rbase = blockIdx.x * 128 + s * 4;

    float acc[4][8];
    #pragma unroll
    for (int rr = 0; rr < 4; rr++)
        #pragma unroll
        for (int j = 0; j < 8; j++) acc[rr][j] = 0.f;

    const float* arow[4];
    #pragma unroll
    for (int rr = 0; rr < 4; rr++) {
        int r = rbase + rr;
        if (r >= VOCAB) r = VOCAB - 1;
        arow[rr] = emb + (size_t)r * EMBED;
    }

    for (int e0 = 0; e0 < EMBED; e0 += 4) {
        float4 av[4];
        #pragma unroll
        for (int rr = 0; rr < 4; rr++)
            av[rr] = *(const float4*)(arow[rr] + e0);

        #pragma unroll
        for (int ee = 0; ee < 4; ee++) {
            const float4 w0 = *(const float4*)&sW[(e0 + ee) * UNITS + ug * 8];
            const float4 w1 = *(const float4*)&sW[(e0 + ee) * UNITS + ug * 8 + 4];
            #pragma unroll
            for (int rr = 0; rr < 4; rr++) {
                const float a = ((const float*)&av[rr])[ee];
                acc[rr][0] = fmaf(a, w0.x, acc[rr][0]);
                acc[rr][1] = fmaf(a, w0.y, acc[rr][1]);
                acc[rr][2] = fmaf(a, w0.z, acc[rr][2]);
                acc[rr][3] = fmaf(a, w0.w, acc[rr][3]);
                acc[rr][4] = fmaf(a, w1.x, acc[rr][4]);
                acc[rr][5] = fmaf(a, w1.y, acc[rr][5]);
                acc[rr][6] = fmaf(a, w1.z, acc[rr][6]);
                acc[rr][7] = fmaf(a, w1.w, acc[rr][7]);
            }
        }
    }

    #pragma unroll
    for (int rr = 0; rr < 4; rr++) {
        const int r = rbase + rr;
        if (r < VOCAB) {
            float4 o0, o1;
            o0.x = acc[rr][0] * TANH_SCALE; o0.y = acc[rr][1] * TANH_SCALE;
            o0.z = acc[rr][2] * TANH_SCALE; o0.w = acc[rr][3] * TANH_SCALE;
            o1.x = acc[rr][4] * TANH_SCALE; o1.y = acc[rr][5] * TANH_SCALE;
            o1.z = acc[rr][6] * TANH_SCALE; o1.w = acc[rr][7] * TANH_SCALE;
            *(float4*)&g_P[r * UNITS + ug * 8]     = o0;
            *(float4*)&g_P[r * UNITS + ug * 8 + 4] = o1;
        }
    }
}

// ---------------------------------------------------------------------------
// Kernel B: recurrence + head. One warp per batch row, lane u owns unit u.
// State r = 1/(1+e^(2x)) (h = 1-2r); affine folded into weights.
// Seeds (xw+cbias) staged in SMEM as [group][lane][4]: ONE LDS.128 per 4
// steps. Step: STS.32 + compiler-barrier (no WARPSYNC; same-warp STS->LDS
// is HW-ordered, proven R7) + 8 LDS.128 broadcast + 32 scalar FMA into 8
// accs + tree + ex2/rcp.
// ---------------------------------------------------------------------------
__global__ void __launch_bounds__(128, 1) rnn_kernel(
    const int*   __restrict__ tokens,
    const float* __restrict__ Wh,
    const float* __restrict__ bvec,
    const float* __restrict__ W1,
    const float* __restrict__ b1,
    const float* __restrict__ W2,
    const float* __restrict__ b2,
    float*       __restrict__ out)
{
    extern __shared__ char dsm[];
    float* sXW  = (float*)(dsm + SMEM_XW);
    int*   sTok = (int*)  (dsm + SMEM_TOK);
    float* sR   = (float*)(dsm + SMEM_R);

    const int tid  = threadIdx.x;
    const int wid  = tid >> 5;
    const int lane = tid & 31;
    const int b0   = blockIdx.x * 4;

    for (int i = tid; i < 4 * MAXLEN; i += 128)
        sTok[i] = tokens[b0 * MAXLEN + i];
    __syncthreads();

    const int* myTok = sTok + wid * MAXLEN;
    float*     myXW  = sXW + wid * (PHASE * UNITS);   // 32KB per warp
    float*     sRrow = sR + wid * UNITS;
    const int  brow  = b0 + wid;

    // Scalar column weights: wh[v] = -2S*Wh[v][lane]; colsum for cbias.
    float wh[32];
    float cs = 0.f;
    #pragma unroll
    for (int v = 0; v < 32; v++) {
        const float w = Wh[v * UNITS + lane];
        cs += w;
        wh[v] = w * (-2.0f * TANH_SCALE);
    }
    const float cbias = (bvec[lane] + cs) * TANH_SCALE;

    const float4* rrow = (const float4*)sRrow;   // 8 x 16B broadcast reads
    float4*       xwq  = (float4*)myXW;          // [group*32 + lane]

    float r = 0.5f;                         // h = 1 - 2r = 0
    for (int p = 0; p < 2; p++) {
        // ---- Stage seeds as quads: group g holds steps 4g..4g+3 ----
        const int4* tokp4 = (const int4*)(myTok + p * PHASE);
        #pragma unroll 4
        for (int t8 = 0; t8 < PHASE / 8; t8++) {
            const int4 ta = tokp4[2 * t8];
            const int4 tb = tokp4[2 * t8 + 1];
            const float v0 = g_P[ta.x * UNITS + lane];
            const float v1 = g_P[ta.y * UNITS + lane];
            const float v2 = g_P[ta.z * UNITS + lane];
            const float v3 = g_P[ta.w * UNITS + lane];
            const float v4 = g_P[tb.x * UNITS + lane];
            const float v5 = g_P[tb.y * UNITS + lane];
            const float v6 = g_P[tb.z * UNITS + lane];
            const float v7 = g_P[tb.w * UNITS + lane];
            xwq[(2 * t8)     * 32 + lane] =
                make_float4(v0 + cbias, v1 + cbias, v2 + cbias, v3 + cbias);
            xwq[(2 * t8 + 1) * 32 + lane] =
                make_float4(v4 + cbias, v5 + cbias, v6 + cbias, v7 + cbias);
        }
        __syncwarp();

        // ---- 64 groups x 4 steps off SMEM only ----
        for (int g = 0; g < PHASE / 4; g++) {
            const float4 sdq = xwq[g * 32 + lane];   // lane's 4 seeds, LDS.128
            float sd[4] = {sdq.x, sdq.y, sdq.z, sdq.w};

            #pragma unroll
            for (int j = 0; j < 4; j++) {
                sRrow[lane] = r;
                asm volatile("" ::: "memory");       // order STS before LDS

                const float4 q0 = rrow[0];
                const float4 q1 = rrow[1];
                const float4 q2 = rrow[2];
                const float4 q3 = rrow[3];
                const float4 q4 = rrow[4];
                const float4 q5 = rrow[5];
                const float4 q6 = rrow[6];
                const float4 q7 = rrow[7];

                float a0 = fmaf(q0.x, wh[0],  sd[j]);
                float a1 = q1.x * wh[4];
                float a2 = q2.x * wh[8];
                float a3 = q3.x * wh[12];
                float a4 = q4.x * wh[16];
                float a5 = q5.x * wh[20];
                float a6 = q6.x * wh[24];
                float a7 = q7.x * wh[28];
                a0 = fmaf(q0.y, wh[1],  a0);
                a1 = fmaf(q1.y, wh[5],  a1);
                a2 = fmaf(q2.y, wh[9],  a2);
                a3 = fmaf(q3.y, wh[13], a3);
                a4 = fmaf(q4.y, wh[17], a4);
                a5 = fmaf(q5.y, wh[21], a5);
                a6 = fmaf(q6.y, wh[25], a6);
                a7 = fmaf(q7.y, wh[29], a7);
                a0 = fmaf(q0.z, wh[2],  a0);
                a1 = fmaf(q1.z, wh[6],  a1);
                a2 = fmaf(q2.z, wh[10], a2);
                a3 = fmaf(q3.z, wh[14], a3);
                a4 = fmaf(q4.z, wh[18], a4);
                a5 = fmaf(q5.z, wh[22], a5);
                a6 = fmaf(q6.z, wh[26], a6);
                a7 = fmaf(q7.z, wh[30], a7);
                a0 = fmaf(q0.w, wh[3],  a0);
                a1 = fmaf(q1.w, wh[7],  a1);
                a2 = fmaf(q2.w, wh[11], a2);
                a3 = fmaf(q3.w, wh[15], a3);
                a4 = fmaf(q4.w, wh[19], a4);
                a5 = fmaf(q5.w, wh[23], a5);
                a6 = fmaf(q6.w, wh[27], a6);
                a7 = fmaf(q7.w, wh[31], a7);

                const float z2 = ((a0 + a1) + (a2 + a3)) + ((a4 + a5) + (a6 + a7));
                // r = 1 / (1 + e^(2x)),  z2 = 2*log2(e)*x (prescaled)
                float e, rn;
                asm("ex2.approx.f32 %0, %1;" : "=f"(e) : "f"(z2));
                asm("rcp.approx.f32 %0, %1;" : "=f"(rn) : "f"(e + 1.0f));
                r = rn;
            }
        }
    }

    const float h = fmaf(-2.0f, r, 1.0f);   // final hidden value for lane

    // Head: f = h@W1 + b1 (16), z = f@W2 + b2, out = sigmoid(z)  (one-time)
    float facc = 0.f;
    #pragma unroll
    for (int v = 0; v < 32; v++) {
        const float hv = __shfl_sync(0xffffffffu, h, v);
        if (lane < F1)
            facc = fmaf(hv, W1[v * F1 + lane], facc);
    }
    float p = 0.f;
    if (lane < F1) p = (facc + b1[lane]) * W2[lane];
    #pragma unroll
    for (int off = 16; off > 0; off >>= 1)
        p += __shfl_xor_sync(0xffffffffu, p, off);

    if (lane == 0) {
        const float z = p + b2[0];
        float e, rr;
        asm("ex2.approx.f32 %0, %1;" : "=f"(e) : "f"(-z * 1.4426950408889634f));
        asm("rcp.approx.f32 %0, %1;" : "=f"(rr) : "f"(1.0f + e));
        out[brow] = rr;
    }
}

// ---------------------------------------------------------------------------
extern "C" void kernel_launch(void* const* d_in, const int* in_sizes, int n_in,
                              void* d_out, int out_size)
{
    const int*   tokens = (const int*)  d_in[0];
    const float* emb    = (const float*)d_in[1];
    const float* Wx     = (const float*)d_in[2];
    const float* Wh     = (const float*)d_in[3];
    const float* b      = (const float*)d_in[4];
    const float* W1     = (const float*)d_in[5];
    const float* b1     = (const float*)d_in[6];
    const float* W2     = (const float*)d_in[7];
    const float* b2     = (const float*)d_in[8];
    float* out = (float*)d_out;

    // Opt-in to >48KB dynamic SMEM (host attribute; idempotent, capture-safe).
    static int attr_done = 0;
    if (!attr_done) {
        cudaFuncSetAttribute(rnn_kernel,
                             cudaFuncAttributeMaxDynamicSharedMemorySize,
                             SMEM_TOTAL);
        attr_done = 1;
    }

    proj_kernel<<<(VOCAB + 127) / 128, 128>>>(emb, Wx);
    rnn_kernel<<<BATCH / 4, 128, SMEM_TOTAL>>>(tokens, Wh, b, W1, b1, W2, b2, out);
}

// round 15
// speedup vs baseline: 1.0833x; 1.0833x over previous
#include <cuda_runtime.h>
#include <cstdint>

#define VOCAB  50000
#define EMBED  256
#define MAXLEN 512
#define UNITS  32
#define F1     16
#define BATCH  512

// Scratch: projected embedding table P[v][u] = sum_e emb[v][e]*Wx[e][u], prescaled
// by 2*log2(e) so the recurrence can feed ex2 directly.
__device__ float g_P[VOCAB * UNITS];

#define TANH_SCALE 2.8853900817779268f   // 2*log2(e)

// ---------------------------------------------------------------------------
// Kernel A: P = (emb_table @ Wx) * TANH_SCALE  (scalar; measured ~13us, at
// the fp32 FMA-issue floor for 0.41G MACs; not the bottleneck)
// ---------------------------------------------------------------------------
__global__ void __launch_bounds__(128) proj_kernel(
    const float* __restrict__ emb, const float* __restrict__ Wx)
{
    __shared__ float sW[EMBED * UNITS];
    const int t = threadIdx.x;
    for (int i = t; i < EMBED * UNITS / 4; i += 128)
        ((float4*)sW)[i] = ((const float4*)Wx)[i];
    __syncthreads();

    const int ug    = t & 3;
    const int s     = t >> 2;
    const int rbase = blockIdx.x * 128 + s * 4;

    float acc[4][8];
    #pragma unroll
    for (int rr = 0; rr < 4; rr++)
        #pragma unroll
        for (int j = 0; j < 8; j++) acc[rr][j] = 0.f;

    const float* arow[4];
    #pragma unroll
    for (int rr = 0; rr < 4; rr++) {
        int r = rbase + rr;
        if (r >= VOCAB) r = VOCAB - 1;
        arow[rr] = emb + (size_t)r * EMBED;
    }

    for (int e0 = 0; e0 < EMBED; e0 += 4) {
        float4 av[4];
        #pragma unroll
        for (int rr = 0; rr < 4; rr++)
            av[rr] = *(const float4*)(arow[rr] + e0);

        #pragma unroll
        for (int ee = 0; ee < 4; ee++) {
            const float4 w0 = *(const float4*)&sW[(e0 + ee) * UNITS + ug * 8];
            const float4 w1 = *(const float4*)&sW[(e0 + ee) * UNITS + ug * 8 + 4];
            #pragma unroll
            for (int rr = 0; rr < 4; rr++) {
                const float a = ((const float*)&av[rr])[ee];
                acc[rr][0] = fmaf(a, w0.x, acc[rr][0]);
                acc[rr][1] = fmaf(a, w0.y, acc[rr][1]);
                acc[rr][2] = fmaf(a, w0.z, acc[rr][2]);
                acc[rr][3] = fmaf(a, w0.w, acc[rr][3]);
                acc[rr][4] = fmaf(a, w1.x, acc[rr][4]);
                acc[rr][5] = fmaf(a, w1.y, acc[rr][5]);
                acc[rr][6] = fmaf(a, w1.z, acc[rr][6]);
                acc[rr][7] = fmaf(a, w1.w, acc[rr][7]);
            }
        }
    }

    #pragma unroll
    for (int rr = 0; rr < 4; rr++) {
        const int r = rbase + rr;
        if (r < VOCAB) {
            float4 o0, o1;
            o0.x = acc[rr][0] * TANH_SCALE; o0.y = acc[rr][1] * TANH_SCALE;
            o0.z = acc[rr][2] * TANH_SCALE; o0.w = acc[rr][3] * TANH_SCALE;
            o1.x = acc[rr][4] * TANH_SCALE; o1.y = acc[rr][5] * TANH_SCALE;
            o1.z = acc[rr][6] * TANH_SCALE; o1.w = acc[rr][7] * TANH_SCALE;
            *(float4*)&g_P[r * UNITS + ug * 8]     = o0;
            *(float4*)&g_P[r * UNITS + ug * 8 + 4] = o1;
        }
    }
}

// ---------------------------------------------------------------------------
// Kernel B: recurrence + head. ONE ROW PER BLOCK, 2 warps (64 threads).
// Output unit u = 16*warp + (lane>>1); half hf = lane&1 owns inputs
// v in [16hf, 16hf+16). Per step each lane does 4 LDS.128 + 16 FMA (4 accs)
// + 2-level tree, then shfl.bfly(1) combines the two half-sums; both lanes
// of a pair redundantly compute r = 1/(1+e^(2x)). Even lanes publish r to a
// PARITY DOUBLE-BUFFERED sR row; one __syncthreads per step orders it.
// Affine fold: sum_v h[v]Wh[v][u] = colsum[u] - 2*sum_v r[v]Wh[v][u].
// ---------------------------------------------------------------------------
__global__ void __launch_bounds__(64) rnn_kernel(
    const int*   __restrict__ tokens,
    const float* __restrict__ Wh,
    const float* __restrict__ bvec,
    const float* __restrict__ W1,
    const float* __restrict__ b1,
    const float* __restrict__ W2,
    const float* __restrict__ b2,
    float*       __restrict__ out)
{
    __shared__ int   sTok[MAXLEN];
    __shared__ float sR[2][UNITS];    // parity double-buffer, 128B rows
    __shared__ float sH[UNITS];

    const int tid = threadIdx.x;
    const int w   = tid >> 5;
    const int ln  = tid & 31;
    const int u   = 16 * w + (ln >> 1);    // output unit this lane computes
    const int hf  = ln & 1;                // input half this lane sums
    const int brow = blockIdx.x;

    for (int i = tid; i < MAXLEN; i += 64)
        sTok[i] = tokens[brow * MAXLEN + i];
    __syncthreads();

    // Column weights for this lane's half: wh[k] = -2S*Wh[16hf+k][u]
    float wh[16];
    float cshalf = 0.f;
    #pragma unroll
    for (int k = 0; k < 16; k++) {
        const float wv = Wh[(16 * hf + k) * UNITS + u];
        cshalf += wv;
        wh[k] = wv * (-2.0f * TANH_SCALE);
    }
    const float cs = cshalf + __shfl_xor_sync(0xffffffffu, cshalf, 1);
    const float cbias = (bvec[u] + cs) * TANH_SCALE;

    const int4* tok4 = (const int4*)sTok;
    const int   NG   = MAXLEN / 4;

    // Prime group 0 seeds (P rows at unit u; pair lanes load same addr).
    int4  tk = tok4[0];
    float c0 = g_P[tk.x * UNITS + u];
    float c1 = g_P[tk.y * UNITS + u];
    float c2 = g_P[tk.z * UNITS + u];
    float c3 = g_P[tk.w * UNITS + u];

    float r = 0.5f;                        // h = 1 - 2r = 0
    for (int g = 0; g < NG; g++) {
        const int gn = (g + 1 < NG) ? (g + 1) : g;     // uniform clamp
        const int4 tkn = tok4[gn];
        const float n0 = g_P[tkn.x * UNITS + u];
        const float n1 = g_P[tkn.y * UNITS + u];
        const float n2 = g_P[tkn.z * UNITS + u];
        const float n3 = g_P[tkn.w * UNITS + u];

        // Seed enters only the hf==0 partial (bfly sums both halves).
        float sd[4];
        sd[0] = (hf == 0) ? (c0 + cbias) : 0.f;
        sd[1] = (hf == 0) ? (c1 + cbias) : 0.f;
        sd[2] = (hf == 0) ? (c2 + cbias) : 0.f;
        sd[3] = (hf == 0) ? (c3 + cbias) : 0.f;

        #pragma unroll
        for (int j = 0; j < 4; j++) {
            float* buf = sR[j & 1];        // static parity per unrolled step
            if (hf == 0) buf[u] = r;       // 32 distinct writers cover all u
            __syncthreads();

            const float4* rq = (const float4*)buf;
            const float4 q0 = rq[hf * 4 + 0];
            const float4 q1 = rq[hf * 4 + 1];
            const float4 q2 = rq[hf * 4 + 2];
            const float4 q3 = rq[hf * 4 + 3];

            float a0 = fmaf(q0.x, wh[0],  sd[j]);
            float a1 = q1.x * wh[4];
            float a2 = q2.x * wh[8];
            float a3 = q3.x * wh[12];
            a0 = fmaf(q0.y, wh[1],  a0);
            a1 = fmaf(q1.y, wh[5],  a1);
            a2 = fmaf(q2.y, wh[9],  a2);
            a3 = fmaf(q3.y, wh[13], a3);
            a0 = fmaf(q0.z, wh[2],  a0);
            a1 = fmaf(q1.z, wh[6],  a1);
            a2 = fmaf(q2.z, wh[10], a2);
            a3 = fmaf(q3.z, wh[14], a3);
            a0 = fmaf(q0.w, wh[3],  a0);
            a1 = fmaf(q1.w, wh[7],  a1);
            a2 = fmaf(q2.w, wh[11], a2);
            a3 = fmaf(q3.w, wh[15], a3);

            const float part = (a0 + a1) + (a2 + a3);
            const float z2 = part + __shfl_xor_sync(0xffffffffu, part, 1);
            // r = 1 / (1 + e^(2x)),  z2 = 2*log2(e)*preact (prescaled)
            float e, rn;
            asm("ex2.approx.f32 %0, %1;" : "=f"(e) : "f"(z2));
            asm("rcp.approx.f32 %0, %1;" : "=f"(rn) : "f"(e + 1.0f));
            r = rn;
        }

        c0 = n0; c1 = n1; c2 = n2; c3 = n3;
    }

    // Publish final hidden values; head on warp 0.
    if (hf == 0) sH[u] = fmaf(-2.0f, r, 1.0f);
    __syncthreads();

    if (w == 0) {
        float facc = 0.f;
        #pragma unroll
        for (int v = 0; v < 32; v++) {
            const float hv = sH[v];            // uniform broadcast
            if (ln < F1)
                facc = fmaf(hv, W1[v * F1 + ln], facc);
        }
        float p = 0.f;
        if (ln < F1) p = (facc + b1[ln]) * W2[ln];
        #pragma unroll
        for (int off = 16; off > 0; off >>= 1)
            p += __shfl_xor_sync(0xffffffffu, p, off);

        if (ln == 0) {
            const float z = p + b2[0];
            float e, rr;
            asm("ex2.approx.f32 %0, %1;" : "=f"(e) : "f"(-z * 1.4426950408889634f));
            asm("rcp.approx.f32 %0, %1;" : "=f"(rr) : "f"(1.0f + e));
            out[brow] = rr;
        }
    }
}

// ---------------------------------------------------------------------------
extern "C" void kernel_launch(void* const* d_in, const int* in_sizes, int n_in,
                              void* d_out, int out_size)
{
    const int*   tokens = (const int*)  d_in[0];
    const float* emb    = (const float*)d_in[1];
    const float* Wx     = (const float*)d_in[2];
    const float* Wh     = (const float*)d_in[3];
    const float* b      = (const float*)d_in[4];
    const float* W1     = (const float*)d_in[5];
    const float* b1     = (const float*)d_in[6];
    const float* W2     = (const float*)d_in[7];
    const float* b2     = (const float*)d_in[8];
    float* out = (float*)d_out;

    proj_kernel<<<(VOCAB + 127) / 128, 128>>>(emb, Wx);
    rnn_kernel<<<BATCH, 64>>>(tokens, Wh, b, W1, b1, W2, b2, out);
}